// round 14
// baseline (speedup 1.0000x reference)
#include <cuda_runtime.h>
#include <math.h>

// SimilarityTreeLSTM on GB300: persistent kernel, hybrid scheduler.
//
// R14 = R13 (CSR gather, no atomics in recurrence, no state zero-init) with:
//  * hybrid scheduling: height-frontier barriered rounds while cnt >= TQ
//    (dense, well-batched), then an R11-style dataflow queue for the tail
//    (valid-entry protocol, claim 4, NT<=4) -- removes ~20 tail rounds'
//    barriers + wave latency.
//  * strict fencing on push path (fence->sub; last child fence->exch entry;
//    consumer volatile read -> fence).
//  * all g_order reads bypass L1 (cross-SM store staleness hazard).

#define NNODE 65536
#define TOT   (2 * NNODE)
#define M     256
#define M3    (3 * M)
#define VOCAB 1000
#define VNB   8
#define TQ    256

// ---------------- device scratch (static: no allocations allowed) ----------
__device__ float g_h[TOT * M];           // internal node h (written once)
__device__ float g_fc[TOT * M];          // internal node f*c (written once)
__device__ float g_ioux[VOCAB * M3];     // vocab proj: emb@Wioux + bioux
__device__ float g_fxp[VOCAB * M];       // vocab proj: emb@Wfx + bfx
__device__ float g_hleaf[VOCAB * M];     // leaf h by token
__device__ float g_cleaf[VOCAB * M];     // leaf c by token
__device__ float g_hfw[VOCAB * M];       // h_leaf @ Wfh + bfh
__device__ int   g_nchild[TOT];
__device__ int   g_pend[TOT];            // remaining internal children
__device__ int   g_cstart[TOT];          // CSR segment start
__device__ int   g_ccur[TOT];            // CSR fill cursor
__device__ int   g_child[TOT];           // CSR entries (<0: leaf, low bits=token)
__device__ int   g_bsum[1024];           // per-block partial sums for scan
__device__ int   g_order[TOT];           // ready list (-1 = not yet filled)
__device__ int   g_alloc;                // next free slot in g_order
__device__ int   g_re;                   // round-end snapshot (set in barrier)
__device__ int   g_qhead;                // queue-mode consumption cursor
__device__ int   g_nint;                 // total internal nodes
__device__ float g_croot[2 * M];
__device__ unsigned g_barcnt;
__device__ unsigned g_sense;

__device__ __forceinline__ float sigf(float x) {
    return 1.0f / (1.0f + expf(-x));
}

// Sense-reversal grid barrier; last arriver snapshots g_alloc into g_re.
__device__ __forceinline__ void gsync() {
    __syncthreads();
    if (threadIdx.x == 0) {
        __threadfence();
        unsigned target = *((volatile unsigned*)&g_sense) + 1u;
        unsigned a = atomicAdd(&g_barcnt, 1u);
        if (a == gridDim.x - 1u) {
            g_barcnt = 0u;
            g_re = *((volatile int*)&g_alloc);
            __threadfence();
            atomicExch(&g_sense, target);
        } else {
            while (*((volatile unsigned*)&g_sense) != target) { __nanosleep(64); }
        }
        __threadfence();
    }
    __syncthreads();
}

// Process one batch of nn nodes; caller pre-filled s_node[t] (clamped) for t<NT.
template <int NT>
__device__ void do_group(int nn,
                         const int* __restrict__ l_tok, const int* __restrict__ l_par,
                         const int* __restrict__ r_tok, const int* __restrict__ r_par,
                         const float* __restrict__ Wiouh, const float* __restrict__ Wfh,
                         float bio0, float bio1, float bio2, float bfh_t,
                         float* s_f, float* s_fc,
                         int* s_node, int* s_tok, int* s_parg, int* s_ptok,
                         int* s_cs, int* s_ce)
{
    const int t = threadIdx.x;

    if (t < NT) {
        int node = s_node[t];
        int tree = node >> 16, loc = node & (NNODE - 1);
        const int* tokp = tree ? r_tok : l_tok;
        const int* parp = tree ? r_par : l_par;
        int pl = parp[loc];
        s_tok[t]  = tokp[loc];
        s_parg[t] = (tree << 16) + pl;
        s_ptok[t] = tokp[pl];
        s_cs[t]   = __ldcg(&g_cstart[node]);
        s_ce[t]   = s_cs[t] + __ldcg(&g_nchild[node]);
    }
    __syncthreads();

    // gather children: leaves from vocab tables, internal from g_h/g_fc
    #pragma unroll
    for (int n = 0; n < NT; n++) {
        float hs = 0.f, fcs = 0.f;
        const float fxv = g_fxp[s_tok[n] * M + t];
        const int ce = s_ce[n];
        for (int j = s_cs[n]; j < ce; j++) {
            int e = __ldg(&g_child[j]);
            if (e < 0) {
                int v = e & 0xFFFF;
                hs  += g_hleaf[v * M + t];
                fcs += sigf(g_hfw[v * M + t] + fxv) * g_cleaf[v * M + t];
            } else {
                hs  += __ldcg(&g_h[(long)e * M + t]);
                fcs += __ldcg(&g_fc[(long)e * M + t]);
            }
        }
        s_f[n * M + t]  = hs;
        s_fc[n * M + t] = fcs;
    }
    __syncthreads();

    float a0[NT], a1[NT], a2[NT];
    #pragma unroll
    for (int n = 0; n < NT; n++) {
        int tk = s_tok[n];
        a0[n] = g_ioux[tk * M3 + t]         + bio0;
        a1[n] = g_ioux[tk * M3 + M + t]     + bio1;
        a2[n] = g_ioux[tk * M3 + 2 * M + t] + bio2;
    }

    // ---- Wiouh matvec: explicit two-phase weight double-buffer ----
    {
        float wa0[4], wa1[4], wa2[4], wb0[4], wb1[4], wb2[4];
        #pragma unroll
        for (int kk = 0; kk < 4; kk++) {
            wa0[kk] = Wiouh[kk * M3 + t];
            wa1[kk] = Wiouh[kk * M3 + M + t];
            wa2[kk] = Wiouh[kk * M3 + 2 * M + t];
        }
        #pragma unroll 1
        for (int k = 0; k < M; k += 8) {
            #pragma unroll
            for (int kk = 0; kk < 4; kk++) {
                wb0[kk] = Wiouh[(k + 4 + kk) * M3 + t];
                wb1[kk] = Wiouh[(k + 4 + kk) * M3 + M + t];
                wb2[kk] = Wiouh[(k + 4 + kk) * M3 + 2 * M + t];
            }
            #pragma unroll
            for (int n = 0; n < NT; n++) {
                const float4 h4 = *reinterpret_cast<const float4*>(s_f + n * M + k);
                a0[n] += h4.x * wa0[0]; a1[n] += h4.x * wa1[0]; a2[n] += h4.x * wa2[0];
                a0[n] += h4.y * wa0[1]; a1[n] += h4.y * wa1[1]; a2[n] += h4.y * wa2[1];
                a0[n] += h4.z * wa0[2]; a1[n] += h4.z * wa1[2]; a2[n] += h4.z * wa2[2];
                a0[n] += h4.w * wa0[3]; a1[n] += h4.w * wa1[3]; a2[n] += h4.w * wa2[3];
            }
            if (k + 8 < M) {
                #pragma unroll
                for (int kk = 0; kk < 4; kk++) {
                    wa0[kk] = Wiouh[(k + 8 + kk) * M3 + t];
                    wa1[kk] = Wiouh[(k + 8 + kk) * M3 + M + t];
                    wa2[kk] = Wiouh[(k + 8 + kk) * M3 + 2 * M + t];
                }
            }
            #pragma unroll
            for (int n = 0; n < NT; n++) {
                const float4 h4 = *reinterpret_cast<const float4*>(s_f + n * M + k + 4);
                a0[n] += h4.x * wb0[0]; a1[n] += h4.x * wb1[0]; a2[n] += h4.x * wb2[0];
                a0[n] += h4.y * wb0[1]; a1[n] += h4.y * wb1[1]; a2[n] += h4.y * wb2[1];
                a0[n] += h4.z * wb0[2]; a1[n] += h4.z * wb1[2]; a2[n] += h4.z * wb2[2];
                a0[n] += h4.w * wb0[3]; a1[n] += h4.w * wb1[3]; a2[n] += h4.w * wb2[3];
            }
        }
    }

    float cv[NT], hv[NT];
    #pragma unroll
    for (int n = 0; n < NT; n++) {
        float fc = s_fc[n * M + t];
        float ig = sigf(a0[n]);
        float og = sigf(a1[n]);
        float ug = tanhf(a2[n]);
        cv[n] = ig * ug + fc;
        hv[n] = og * tanhf(cv[n]);
    }
    __syncthreads();                 // s_f reuse boundary
    #pragma unroll
    for (int n = 0; n < NT; n++) s_f[n * M + t] = hv[n];
    __syncthreads();

    float b[NT];
    #pragma unroll
    for (int n = 0; n < NT; n++)
        b[n] = bfh_t + g_fxp[s_ptok[n] * M + t];

    // ---- Wfh matvec: explicit two-phase weight double-buffer ----
    {
        float wa[4], wb[4];
        #pragma unroll
        for (int kk = 0; kk < 4; kk++)
            wa[kk] = Wfh[kk * M + t];
        #pragma unroll 1
        for (int k = 0; k < M; k += 8) {
            #pragma unroll
            for (int kk = 0; kk < 4; kk++)
                wb[kk] = Wfh[(k + 4 + kk) * M + t];
            #pragma unroll
            for (int n = 0; n < NT; n++) {
                const float4 h4 = *reinterpret_cast<const float4*>(s_f + n * M + k);
                b[n] += h4.x * wa[0] + h4.y * wa[1] + h4.z * wa[2] + h4.w * wa[3];
            }
            if (k + 8 < M) {
                #pragma unroll
                for (int kk = 0; kk < 4; kk++)
                    wa[kk] = Wfh[(k + 8 + kk) * M + t];
            }
            #pragma unroll
            for (int n = 0; n < NT; n++) {
                const float4 h4 = *reinterpret_cast<const float4*>(s_f + n * M + k + 4);
                b[n] += h4.x * wb[0] + h4.y * wb[1] + h4.z * wb[2] + h4.w * wb[3];
            }
        }
    }

    // plain stores (no atomics): each internal node writes its own rows
    #pragma unroll
    for (int n = 0; n < NT; n++) {
        if (n < nn) {
            int node = s_node[n];
            if (node & (NNODE - 1)) {        // not a root
                float f = sigf(b[n]);
                g_h[(long)node * M + t]  = hv[n];
                g_fc[(long)node * M + t] = f * cv[n];
            } else {
                g_croot[(node >> 16) * M + t] = cv[n];
            }
        }
    }
    __threadfence();                 // release: data before pend decrement
    __syncthreads();
    if (t < nn) {
        int node = s_node[t];
        if (node & (NNODE - 1)) {
            int pg = s_parg[t];
            if (atomicSub(&g_pend[pg], 1) == 1) {
                __threadfence();     // all children's data visible before push
                int pos = atomicAdd(&g_alloc, 1);
                atomicExch(&g_order[pos], pg);
            }
        }
    }
    __syncthreads();
}

// Round mode: process [rs, rs+cnt) of g_order, NT nodes per group.
template <int NT>
__device__ void do_round(int rs, int cnt,
                         const int* __restrict__ l_tok, const int* __restrict__ l_par,
                         const int* __restrict__ r_tok, const int* __restrict__ r_par,
                         const float* __restrict__ Wiouh, const float* __restrict__ Wfh,
                         float bio0, float bio1, float bio2, float bfh_t,
                         float* s_f, float* s_fc,
                         int* s_node, int* s_tok, int* s_parg, int* s_ptok,
                         int* s_cs, int* s_ce)
{
    const int t = threadIdx.x;
    const int ngrp = (cnt + NT - 1) / NT;
    for (int g = blockIdx.x; g < ngrp; g += gridDim.x) {
        const int base = rs + g * NT;
        const int nn   = min(NT, cnt - g * NT);
        if (t < NT)
            s_node[t] = __ldcg(&g_order[base + ((t < nn) ? t : 0)]);
        do_group<NT>(nn, l_tok, l_par, r_tok, r_par, Wiouh, Wfh,
                     bio0, bio1, bio2, bfh_t, s_f, s_fc,
                     s_node, s_tok, s_parg, s_ptok, s_cs, s_ce);
    }
}

extern "C" __global__ void __launch_bounds__(256, 2)
treelstm_kernel(const int* __restrict__ l_tok, const int* __restrict__ l_par,
                const int* __restrict__ r_tok, const int* __restrict__ r_par,
                const float* __restrict__ emb,
                const float* __restrict__ Wioux, const float* __restrict__ bioux,
                const float* __restrict__ Wiouh, const float* __restrict__ biouh,
                const float* __restrict__ Wfx,   const float* __restrict__ bfx,
                const float* __restrict__ Wfh,   const float* __restrict__ bfh,
                const float* __restrict__ Wh,    const float* __restrict__ bh,
                const float* __restrict__ Wp,    const float* __restrict__ bp,
                float* __restrict__ out)
{
    __shared__ __align__(16) float s_f[16 * M];    // 16 KB
    __shared__ __align__(16) float s_fc[16 * M];   // 16 KB
    __shared__ int s_node[16], s_tok[16], s_parg[16], s_ptok[16];
    __shared__ int s_cs[16], s_ce[16];
    __shared__ int s_red[256];
    __shared__ int sh_pos, sh_nn, sh_more, s_qb[4];

    const int t   = threadIdx.x;
    const int gid = blockIdx.x * blockDim.x + threadIdx.x;
    const int gs  = gridDim.x * blockDim.x;
    const int G   = gridDim.x;

    // ------- Phase 0: init + vocab projections ----------------------------
    {
        for (int i = gid; i < TOT; i += gs) {
            g_nchild[i] = 0; g_pend[i] = 0; g_order[i] = -1;
        }
        if (gid == 0) { g_alloc = 0; g_nint = 0; }

        const int VG = VOCAB / VNB;   // 125
        for (int g = blockIdx.x; g < VG; g += gridDim.x) {
            #pragma unroll
            for (int n = 0; n < VNB; n++)
                s_f[n * M + t] = emb[(g * VNB + n) * M + t];
            __syncthreads();
            float a0[VNB], a1[VNB], a2[VNB], af[VNB];
            #pragma unroll
            for (int n = 0; n < VNB; n++) {
                a0[n] = bioux[t]; a1[n] = bioux[M + t];
                a2[n] = bioux[2 * M + t]; af[n] = bfx[t];
            }
            #pragma unroll 1
            for (int k = 0; k < M; k += 4) {
                #pragma unroll
                for (int kk = 0; kk < 4; kk++) {
                    float w0 = Wioux[(k + kk) * M3 + t];
                    float w1 = Wioux[(k + kk) * M3 + M + t];
                    float w2 = Wioux[(k + kk) * M3 + 2 * M + t];
                    float wf = Wfx[(k + kk) * M + t];
                    #pragma unroll
                    for (int n = 0; n < VNB; n++) {
                        float xv = s_f[n * M + k + kk];
                        a0[n] += xv * w0; a1[n] += xv * w1;
                        a2[n] += xv * w2; af[n] += xv * wf;
                    }
                }
            }
            #pragma unroll
            for (int n = 0; n < VNB; n++) {
                int v = g * VNB + n;
                g_ioux[v * M3 + t]         = a0[n];
                g_ioux[v * M3 + M + t]     = a1[n];
                g_ioux[v * M3 + 2 * M + t] = a2[n];
                g_fxp[v * M + t]           = af[n];
            }
            __syncthreads();
        }
    }
    gsync();

    // loop-invariant biases
    const float bio0 = biouh[t], bio1 = biouh[M + t], bio2 = biouh[2 * M + t];
    const float bfh_t = bfh[t];

    // ------- Phase 1: child counts + leaf h/c tables ----------------------
    for (int i = gid; i < TOT; i += gs) {
        int tree = i >> 16, loc = i & (NNODE - 1);
        if (loc) {
            const int* parp = tree ? r_par : l_par;
            atomicAdd(&g_nchild[(tree << 16) + __ldg(parp + loc)], 1);
        }
    }
    for (int i = gid; i < VOCAB * M; i += gs) {
        int v = i / M, e = i % M;
        float i0 = g_ioux[v * M3 + e]         + biouh[e];
        float i1 = g_ioux[v * M3 + M + e]     + biouh[M + e];
        float i2 = g_ioux[v * M3 + 2 * M + e] + biouh[2 * M + e];
        float c  = sigf(i0) * tanhf(i2);
        g_cleaf[i] = c;
        g_hleaf[i] = sigf(i1) * tanhf(c);
    }
    gsync();

    // ------- Phase 2: pend counts + hfW table + scan part A ---------------
    for (int i = gid; i < TOT; i += gs) {
        int loc = i & (NNODE - 1);
        if (loc && __ldcg(&g_nchild[i]) > 0) {
            int tree = i >> 16;
            const int* parp = tree ? r_par : l_par;
            atomicAdd(&g_pend[(tree << 16) + __ldg(parp + loc)], 1);
        }
    }
    {
        const int VG = VOCAB / VNB;   // 125
        for (int g = blockIdx.x; g < VG; g += gridDim.x) {
            #pragma unroll
            for (int n = 0; n < VNB; n++)
                s_f[n * M + t] = g_hleaf[(g * VNB + n) * M + t];
            __syncthreads();
            float bf[VNB];
            #pragma unroll
            for (int n = 0; n < VNB; n++) bf[n] = bfh_t;
            #pragma unroll 1
            for (int k = 0; k < M; k += 4) {
                #pragma unroll
                for (int kk = 0; kk < 4; kk++) {
                    float w = Wfh[(k + kk) * M + t];
                    #pragma unroll
                    for (int n = 0; n < VNB; n++)
                        bf[n] += s_f[n * M + k + kk] * w;
                }
            }
            #pragma unroll
            for (int n = 0; n < VNB; n++)
                g_hfw[(g * VNB + n) * M + t] = bf[n];
            __syncthreads();
        }
    }
    {
        // per-block partial sum of nchild over its chunk
        const int chunk = (TOT + G - 1) / G;
        const int lo = blockIdx.x * chunk;
        const int hi = min(TOT, lo + chunk);
        int local = 0;
        for (int i = lo + t; i < hi; i += 256) local += __ldcg(&g_nchild[i]);
        s_red[t] = local;
        __syncthreads();
        for (int s = 128; s > 0; s >>= 1) {
            if (t < s) s_red[t] += s_red[t + s];
            __syncthreads();
        }
        if (t == 0) g_bsum[blockIdx.x] = s_red[0];
    }
    gsync();

    // ------- Phase 3: serial scan of block sums (tiny) --------------------
    if (blockIdx.x == 0 && t == 0) {
        int run = 0;
        for (int b = 0; b < G; b++) {
            int s = __ldcg(&g_bsum[b]);
            g_bsum[b] = run;
            run += s;
        }
    }
    gsync();

    // ------- Phase 4a: within-chunk exclusive scan (smem staged) ----------
    {
        const int chunk = (TOT + G - 1) / G;
        const int lo = blockIdx.x * chunk;
        const int hi = min(TOT, lo + chunk);
        int* s_i = reinterpret_cast<int*>(s_f);    // 4096 ints >= chunk
        for (int i = lo + t; i < hi; i += 256) s_i[i - lo] = __ldcg(&g_nchild[i]);
        __syncthreads();
        if (t == 0) {
            int run = __ldcg(&g_bsum[blockIdx.x]);
            for (int i = 0; i < hi - lo; i++) { int c = s_i[i]; s_i[i] = run; run += c; }
        }
        __syncthreads();
        for (int i = lo + t; i < hi; i += 256) {
            g_cstart[i] = s_i[i - lo];
            g_ccur[i]   = s_i[i - lo];
        }
    }
    gsync();

    // ------- Phase 4b: CSR fill + round-0 classify + n_int ----------------
    for (int i = gid; i < TOT; i += gs) {
        int tree = i >> 16, loc = i & (NNODE - 1);
        if (loc) {
            const int* parp = tree ? r_par : l_par;
            const int* tokp = tree ? r_tok : l_tok;
            int pg = (tree << 16) + __ldg(parp + loc);
            int slot = atomicAdd(&g_ccur[pg], 1);
            int isleaf = (__ldcg(&g_nchild[i]) == 0);
            g_child[slot] = isleaf ? (int)(0x80000000u | (unsigned)tokp[loc]) : i;
        }
        if (__ldcg(&g_nchild[i]) > 0) {
            atomicAdd(&g_nint, 1);
            if (__ldcg(&g_pend[i]) == 0)
                g_order[atomicAdd(&g_alloc, 1)] = i;
        }
    }
    gsync();   // snapshots g_alloc -> g_re (round 0 boundary)

    // ------- Phase 5: bulk rounds while cnt >= TQ --------------------------
    int rs = 0;
    int re = __ldcg(&g_re);
    while (rs < re && (re - rs) >= TQ) {
        const int cnt = re - rs;
        // traffic-aware NT pick: cost = batches * max(fma, weights, floor)
        long best = 0x7fffffffffffL; int bestNT = 16;
        #pragma unroll
        for (int ntI = 0; ntI < 3; ntI++) {
            const int NTc = (ntI == 0) ? 16 : (ntI == 1) ? 8 : 4;
            int grp = (cnt + NTc - 1) / NTc;
            int bat = (grp + G - 1) / G;
            int gw  = grp < G ? grp : G;
            int wc  = NTc * 455;
            if (gw * 10 > wc) wc = gw * 10;
            if (wc < 250) wc = 250;
            long c = (long)bat * wc;
            if (c < best) { best = c; bestNT = NTc; }
        }
        if (bestNT == 16)
            do_round<16>(rs, cnt, l_tok, l_par, r_tok, r_par, Wiouh, Wfh,
                         bio0, bio1, bio2, bfh_t, s_f, s_fc,
                         s_node, s_tok, s_parg, s_ptok, s_cs, s_ce);
        else if (bestNT == 8)
            do_round<8>(rs, cnt, l_tok, l_par, r_tok, r_par, Wiouh, Wfh,
                        bio0, bio1, bio2, bfh_t, s_f, s_fc,
                        s_node, s_tok, s_parg, s_ptok, s_cs, s_ce);
        else
            do_round<4>(rs, cnt, l_tok, l_par, r_tok, r_par, Wiouh, Wfh,
                        bio0, bio1, bio2, bfh_t, s_f, s_fc,
                        s_node, s_tok, s_parg, s_ptok, s_cs, s_ce);
        gsync();                      // drains stores + snapshots next re
        rs = re;
        re = __ldcg(&g_re);
    }

    // ------- Phase 5b: dataflow queue for the tail -------------------------
    if (blockIdx.x == 0 && t == 0) g_qhead = rs;
    gsync();
    {
        const int n_int = __ldcg(&g_nint);
        for (;;) {
            if (t == 0) sh_pos = atomicAdd(&g_qhead, 4);
            __syncthreads();
            const int pos = sh_pos;
            __syncthreads();
            if (pos >= n_int) break;
            const int lim = min(4, n_int - pos);

            unsigned consumed = 0;        // meaningful on t==0 only
            int more = 1;
            while (more) {
                if (t == 0) {
                    const unsigned full = (1u << lim) - 1u;
                    int nn = 0;
                    while (nn == 0) {
                        for (int j = 0; j < lim; j++) {
                            if (!(consumed & (1u << j))) {
                                int v = *((volatile int*)&g_order[pos + j]);
                                if (v >= 0) { s_qb[nn++] = v; consumed |= (1u << j); }
                            }
                        }
                        if (nn == 0) __nanosleep(200);
                    }
                    sh_nn = nn;
                    sh_more = (consumed != full) ? 1 : 0;
                }
                __syncthreads();
                const int nn = sh_nn;
                more = sh_more;
                __threadfence();          // acquire: entries -> data reads
                if (nn > 2) {
                    if (t < 4) s_node[t] = s_qb[(t < nn) ? t : 0];
                    do_group<4>(nn, l_tok, l_par, r_tok, r_par, Wiouh, Wfh,
                                bio0, bio1, bio2, bfh_t, s_f, s_fc,
                                s_node, s_tok, s_parg, s_ptok, s_cs, s_ce);
                } else if (nn > 1) {
                    if (t < 2) s_node[t] = s_qb[t];
                    do_group<2>(nn, l_tok, l_par, r_tok, r_par, Wiouh, Wfh,
                                bio0, bio1, bio2, bfh_t, s_f, s_fc,
                                s_node, s_tok, s_parg, s_ptok, s_cs, s_ce);
                } else {
                    if (t < 1) s_node[t] = s_qb[0];
                    do_group<1>(nn, l_tok, l_par, r_tok, r_par, Wiouh, Wfh,
                                bio0, bio1, bio2, bfh_t, s_f, s_fc,
                                s_node, s_tok, s_parg, s_ptok, s_cs, s_ce);
                }
            }
        }
    }
    gsync();

    // ------- Phase 6: similarity head (block 0) ----------------------------
    if (blockIdx.x == 0) {
        float cl = __ldcg(&g_croot[t]);
        float cr = __ldcg(&g_croot[M + t]);
        s_f[t]     = cl * cr;
        s_f[M + t] = fabsf(cl - cr);
        __syncthreads();
        float acc = bh[t];
        for (int k = 0; k < 2 * M; k++) acc += s_f[k] * Wh[k * M + t];
        float hid = sigf(acc);
        s_f[2 * M + t] = hid * Wp[2 * t];
        s_f[3 * M + t] = hid * Wp[2 * t + 1];
        __syncthreads();
        if (t == 0) {
            float l0 = bp[0], l1 = bp[1];
            for (int k = 0; k < M; k++) { l0 += s_f[2 * M + k]; l1 += s_f[3 * M + k]; }
            float mx = fmaxf(l0, l1);
            float e0 = expf(l0 - mx), e1 = expf(l1 - mx);
            float inv = 1.0f / (e0 + e1);
            out[0] = e0 * inv;
            out[1] = e1 * inv;
        }
    }
}

extern "C" void kernel_launch(void* const* d_in, const int* in_sizes, int n_in,
                              void* d_out, int out_size)
{
    (void)in_sizes; (void)n_in; (void)out_size;
    int dev = 0;
    cudaGetDevice(&dev);
    int nsm = 0;
    cudaDeviceGetAttribute(&nsm, cudaDevAttrMultiProcessorCount, dev);
    if (nsm <= 0) nsm = 148;

    treelstm_kernel<<<2 * nsm, 256>>>(
        (const int*)d_in[0], (const int*)d_in[1],
        (const int*)d_in[2], (const int*)d_in[3],
        (const float*)d_in[4],
        (const float*)d_in[5], (const float*)d_in[6],
        (const float*)d_in[7], (const float*)d_in[8],
        (const float*)d_in[9], (const float*)d_in[10],
        (const float*)d_in[11], (const float*)d_in[12],
        (const float*)d_in[13], (const float*)d_in[14],
        (const float*)d_in[15], (const float*)d_in[16],
        (float*)d_out);
}

// round 15
// speedup vs baseline: 1.1520x; 1.1520x over previous
#include <cuda_runtime.h>
#include <math.h>

// SimilarityTreeLSTM on GB300: persistent kernel, height-frontier rounds.
//
// R15 = R13 (CSR gather, plain stores, no state zero-init; queue experiments
// R11/R14 both regressed and are dropped) with intra-round wave splitting:
//  * nodes within one frontier are independent, so each round runs
//    nfull = cnt/(16*G) EXACTLY-FULL NT=16 waves (no imbalance), then ONE
//    remainder wave with NT from the cost model over {16,8,4,2,1} --
//    no barrier between sub-waves. Kills last-wave quantization waste.
//  * all g_order reads use __ldcg (cross-SM store / L1 staleness hazard).

#define NNODE 65536
#define TOT   (2 * NNODE)
#define M     256
#define M3    (3 * M)
#define VOCAB 1000
#define VNB   8

// ---------------- device scratch (static: no allocations allowed) ----------
__device__ float g_h[TOT * M];           // internal node h (written once)
__device__ float g_fc[TOT * M];          // internal node f*c (written once)
__device__ float g_ioux[VOCAB * M3];     // vocab proj: emb@Wioux + bioux
__device__ float g_fxp[VOCAB * M];       // vocab proj: emb@Wfx + bfx
__device__ float g_hleaf[VOCAB * M];     // leaf h by token
__device__ float g_cleaf[VOCAB * M];     // leaf c by token
__device__ float g_hfw[VOCAB * M];       // h_leaf @ Wfh + bfh
__device__ int   g_nchild[TOT];
__device__ int   g_pend[TOT];            // remaining internal children
__device__ int   g_cstart[TOT];          // CSR segment start
__device__ int   g_ccur[TOT];            // CSR fill cursor
__device__ int   g_child[TOT];           // CSR entries (<0: leaf, low bits=token)
__device__ int   g_bsum[1024];           // per-block partial sums for scan
__device__ int   g_order[TOT];           // append-only ready list
__device__ int   g_alloc;                // next free slot in g_order
__device__ int   g_re;                   // round-end snapshot (set in barrier)
__device__ float g_croot[2 * M];
__device__ unsigned g_barcnt;
__device__ unsigned g_sense;

__device__ __forceinline__ float sigf(float x) {
    return 1.0f / (1.0f + expf(-x));
}

// Sense-reversal grid barrier; last arriver snapshots g_alloc into g_re.
__device__ __forceinline__ void gsync() {
    __syncthreads();
    if (threadIdx.x == 0) {
        __threadfence();
        unsigned target = *((volatile unsigned*)&g_sense) + 1u;
        unsigned a = atomicAdd(&g_barcnt, 1u);
        if (a == gridDim.x - 1u) {
            g_barcnt = 0u;
            g_re = *((volatile int*)&g_alloc);
            __threadfence();
            atomicExch(&g_sense, target);
        } else {
            while (*((volatile unsigned*)&g_sense) != target) { __nanosleep(64); }
        }
        __threadfence();
    }
    __syncthreads();
}

// Process one batch of nn nodes; caller pre-filled s_node[t] (clamped) for t<NT.
template <int NT>
__device__ void do_group(int nn,
                         const int* __restrict__ l_tok, const int* __restrict__ l_par,
                         const int* __restrict__ r_tok, const int* __restrict__ r_par,
                         const float* __restrict__ Wiouh, const float* __restrict__ Wfh,
                         float bio0, float bio1, float bio2, float bfh_t,
                         float* s_f, float* s_fc,
                         int* s_node, int* s_tok, int* s_parg, int* s_ptok,
                         int* s_cs, int* s_ce)
{
    const int t = threadIdx.x;

    if (t < NT) {
        int node = s_node[t];
        int tree = node >> 16, loc = node & (NNODE - 1);
        const int* tokp = tree ? r_tok : l_tok;
        const int* parp = tree ? r_par : l_par;
        int pl = parp[loc];
        s_tok[t]  = tokp[loc];
        s_parg[t] = (tree << 16) + pl;
        s_ptok[t] = tokp[pl];
        s_cs[t]   = __ldcg(&g_cstart[node]);
        s_ce[t]   = s_cs[t] + __ldcg(&g_nchild[node]);
    }
    __syncthreads();

    // gather children: leaves from vocab tables, internal from g_h/g_fc
    #pragma unroll
    for (int n = 0; n < NT; n++) {
        float hs = 0.f, fcs = 0.f;
        const float fxv = g_fxp[s_tok[n] * M + t];
        const int ce = s_ce[n];
        for (int j = s_cs[n]; j < ce; j++) {
            int e = __ldg(&g_child[j]);
            if (e < 0) {
                int v = e & 0xFFFF;
                hs  += g_hleaf[v * M + t];
                fcs += sigf(g_hfw[v * M + t] + fxv) * g_cleaf[v * M + t];
            } else {
                hs  += __ldcg(&g_h[(long)e * M + t]);
                fcs += __ldcg(&g_fc[(long)e * M + t]);
            }
        }
        s_f[n * M + t]  = hs;
        s_fc[n * M + t] = fcs;
    }
    __syncthreads();

    float a0[NT], a1[NT], a2[NT];
    #pragma unroll
    for (int n = 0; n < NT; n++) {
        int tk = s_tok[n];
        a0[n] = g_ioux[tk * M3 + t]         + bio0;
        a1[n] = g_ioux[tk * M3 + M + t]     + bio1;
        a2[n] = g_ioux[tk * M3 + 2 * M + t] + bio2;
    }

    // ---- Wiouh matvec: explicit two-phase weight double-buffer ----
    {
        float wa0[4], wa1[4], wa2[4], wb0[4], wb1[4], wb2[4];
        #pragma unroll
        for (int kk = 0; kk < 4; kk++) {
            wa0[kk] = Wiouh[kk * M3 + t];
            wa1[kk] = Wiouh[kk * M3 + M + t];
            wa2[kk] = Wiouh[kk * M3 + 2 * M + t];
        }
        #pragma unroll 1
        for (int k = 0; k < M; k += 8) {
            #pragma unroll
            for (int kk = 0; kk < 4; kk++) {
                wb0[kk] = Wiouh[(k + 4 + kk) * M3 + t];
                wb1[kk] = Wiouh[(k + 4 + kk) * M3 + M + t];
                wb2[kk] = Wiouh[(k + 4 + kk) * M3 + 2 * M + t];
            }
            #pragma unroll
            for (int n = 0; n < NT; n++) {
                const float4 h4 = *reinterpret_cast<const float4*>(s_f + n * M + k);
                a0[n] += h4.x * wa0[0]; a1[n] += h4.x * wa1[0]; a2[n] += h4.x * wa2[0];
                a0[n] += h4.y * wa0[1]; a1[n] += h4.y * wa1[1]; a2[n] += h4.y * wa2[1];
                a0[n] += h4.z * wa0[2]; a1[n] += h4.z * wa1[2]; a2[n] += h4.z * wa2[2];
                a0[n] += h4.w * wa0[3]; a1[n] += h4.w * wa1[3]; a2[n] += h4.w * wa2[3];
            }
            if (k + 8 < M) {
                #pragma unroll
                for (int kk = 0; kk < 4; kk++) {
                    wa0[kk] = Wiouh[(k + 8 + kk) * M3 + t];
                    wa1[kk] = Wiouh[(k + 8 + kk) * M3 + M + t];
                    wa2[kk] = Wiouh[(k + 8 + kk) * M3 + 2 * M + t];
                }
            }
            #pragma unroll
            for (int n = 0; n < NT; n++) {
                const float4 h4 = *reinterpret_cast<const float4*>(s_f + n * M + k + 4);
                a0[n] += h4.x * wb0[0]; a1[n] += h4.x * wb1[0]; a2[n] += h4.x * wb2[0];
                a0[n] += h4.y * wb0[1]; a1[n] += h4.y * wb1[1]; a2[n] += h4.y * wb2[1];
                a0[n] += h4.z * wb0[2]; a1[n] += h4.z * wb1[2]; a2[n] += h4.z * wb2[2];
                a0[n] += h4.w * wb0[3]; a1[n] += h4.w * wb1[3]; a2[n] += h4.w * wb2[3];
            }
        }
    }

    float cv[NT], hv[NT];
    #pragma unroll
    for (int n = 0; n < NT; n++) {
        float fc = s_fc[n * M + t];
        float ig = sigf(a0[n]);
        float og = sigf(a1[n]);
        float ug = tanhf(a2[n]);
        cv[n] = ig * ug + fc;
        hv[n] = og * tanhf(cv[n]);
    }
    __syncthreads();                 // s_f reuse boundary
    #pragma unroll
    for (int n = 0; n < NT; n++) s_f[n * M + t] = hv[n];
    __syncthreads();

    float b[NT];
    #pragma unroll
    for (int n = 0; n < NT; n++)
        b[n] = bfh_t + g_fxp[s_ptok[n] * M + t];

    // ---- Wfh matvec: explicit two-phase weight double-buffer ----
    {
        float wa[4], wb[4];
        #pragma unroll
        for (int kk = 0; kk < 4; kk++)
            wa[kk] = Wfh[kk * M + t];
        #pragma unroll 1
        for (int k = 0; k < M; k += 8) {
            #pragma unroll
            for (int kk = 0; kk < 4; kk++)
                wb[kk] = Wfh[(k + 4 + kk) * M + t];
            #pragma unroll
            for (int n = 0; n < NT; n++) {
                const float4 h4 = *reinterpret_cast<const float4*>(s_f + n * M + k);
                b[n] += h4.x * wa[0] + h4.y * wa[1] + h4.z * wa[2] + h4.w * wa[3];
            }
            if (k + 8 < M) {
                #pragma unroll
                for (int kk = 0; kk < 4; kk++)
                    wa[kk] = Wfh[(k + 8 + kk) * M + t];
            }
            #pragma unroll
            for (int n = 0; n < NT; n++) {
                const float4 h4 = *reinterpret_cast<const float4*>(s_f + n * M + k + 4);
                b[n] += h4.x * wb[0] + h4.y * wb[1] + h4.z * wb[2] + h4.w * wb[3];
            }
        }
    }

    // plain stores (no atomics): each internal node writes its own rows
    #pragma unroll
    for (int n = 0; n < NT; n++) {
        if (n < nn) {
            int node = s_node[n];
            if (node & (NNODE - 1)) {        // not a root
                float f = sigf(b[n]);
                g_h[(long)node * M + t]  = hv[n];
                g_fc[(long)node * M + t] = f * cv[n];
            } else {
                g_croot[(node >> 16) * M + t] = cv[n];
            }
        }
    }
    __syncthreads();
    // last-finishing child pushes parent (consumed only after next gsync,
    // whose fences make both the data stores and this push visible)
    if (t < nn) {
        int node = s_node[t];
        if (node & (NNODE - 1)) {
            int pg = s_parg[t];
            if (atomicSub(&g_pend[pg], 1) == 1) {
                int pos = atomicAdd(&g_alloc, 1);
                g_order[pos] = pg;
            }
        }
    }
    __syncthreads();
}

// Round mode: process [rs, rs+cnt) of g_order, NT nodes per group.
template <int NT>
__device__ void do_round(int rs, int cnt,
                         const int* __restrict__ l_tok, const int* __restrict__ l_par,
                         const int* __restrict__ r_tok, const int* __restrict__ r_par,
                         const float* __restrict__ Wiouh, const float* __restrict__ Wfh,
                         float bio0, float bio1, float bio2, float bfh_t,
                         float* s_f, float* s_fc,
                         int* s_node, int* s_tok, int* s_parg, int* s_ptok,
                         int* s_cs, int* s_ce)
{
    const int t = threadIdx.x;
    const int ngrp = (cnt + NT - 1) / NT;
    for (int g = blockIdx.x; g < ngrp; g += gridDim.x) {
        const int base = rs + g * NT;
        const int nn   = min(NT, cnt - g * NT);
        if (t < NT)
            s_node[t] = __ldcg(&g_order[base + ((t < nn) ? t : 0)]);
        do_group<NT>(nn, l_tok, l_par, r_tok, r_par, Wiouh, Wfh,
                     bio0, bio1, bio2, bfh_t, s_f, s_fc,
                     s_node, s_tok, s_parg, s_ptok, s_cs, s_ce);
    }
}

extern "C" __global__ void __launch_bounds__(256, 2)
treelstm_kernel(const int* __restrict__ l_tok, const int* __restrict__ l_par,
                const int* __restrict__ r_tok, const int* __restrict__ r_par,
                const float* __restrict__ emb,
                const float* __restrict__ Wioux, const float* __restrict__ bioux,
                const float* __restrict__ Wiouh, const float* __restrict__ biouh,
                const float* __restrict__ Wfx,   const float* __restrict__ bfx,
                const float* __restrict__ Wfh,   const float* __restrict__ bfh,
                const float* __restrict__ Wh,    const float* __restrict__ bh,
                const float* __restrict__ Wp,    const float* __restrict__ bp,
                float* __restrict__ out)
{
    __shared__ __align__(16) float s_f[16 * M];    // 16 KB
    __shared__ __align__(16) float s_fc[16 * M];   // 16 KB
    __shared__ int s_node[16], s_tok[16], s_parg[16], s_ptok[16];
    __shared__ int s_cs[16], s_ce[16];
    __shared__ int s_red[256];

    const int t   = threadIdx.x;
    const int gid = blockIdx.x * blockDim.x + threadIdx.x;
    const int gs  = gridDim.x * blockDim.x;
    const int G   = gridDim.x;

    // ------- Phase 0: init + vocab projections ----------------------------
    {
        for (int i = gid; i < TOT; i += gs) { g_nchild[i] = 0; g_pend[i] = 0; }
        if (gid == 0) g_alloc = 0;

        const int VG = VOCAB / VNB;   // 125
        for (int g = blockIdx.x; g < VG; g += gridDim.x) {
            #pragma unroll
            for (int n = 0; n < VNB; n++)
                s_f[n * M + t] = emb[(g * VNB + n) * M + t];
            __syncthreads();
            float a0[VNB], a1[VNB], a2[VNB], af[VNB];
            #pragma unroll
            for (int n = 0; n < VNB; n++) {
                a0[n] = bioux[t]; a1[n] = bioux[M + t];
                a2[n] = bioux[2 * M + t]; af[n] = bfx[t];
            }
            #pragma unroll 1
            for (int k = 0; k < M; k += 4) {
                #pragma unroll
                for (int kk = 0; kk < 4; kk++) {
                    float w0 = Wioux[(k + kk) * M3 + t];
                    float w1 = Wioux[(k + kk) * M3 + M + t];
                    float w2 = Wioux[(k + kk) * M3 + 2 * M + t];
                    float wf = Wfx[(k + kk) * M + t];
                    #pragma unroll
                    for (int n = 0; n < VNB; n++) {
                        float xv = s_f[n * M + k + kk];
                        a0[n] += xv * w0; a1[n] += xv * w1;
                        a2[n] += xv * w2; af[n] += xv * wf;
                    }
                }
            }
            #pragma unroll
            for (int n = 0; n < VNB; n++) {
                int v = g * VNB + n;
                g_ioux[v * M3 + t]         = a0[n];
                g_ioux[v * M3 + M + t]     = a1[n];
                g_ioux[v * M3 + 2 * M + t] = a2[n];
                g_fxp[v * M + t]           = af[n];
            }
            __syncthreads();
        }
    }
    gsync();

    // loop-invariant biases
    const float bio0 = biouh[t], bio1 = biouh[M + t], bio2 = biouh[2 * M + t];
    const float bfh_t = bfh[t];

    // ------- Phase 1: child counts + leaf h/c tables ----------------------
    for (int i = gid; i < TOT; i += gs) {
        int tree = i >> 16, loc = i & (NNODE - 1);
        if (loc) {
            const int* parp = tree ? r_par : l_par;
            atomicAdd(&g_nchild[(tree << 16) + __ldg(parp + loc)], 1);
        }
    }
    for (int i = gid; i < VOCAB * M; i += gs) {
        int v = i / M, e = i % M;
        float i0 = g_ioux[v * M3 + e]         + biouh[e];
        float i1 = g_ioux[v * M3 + M + e]     + biouh[M + e];
        float i2 = g_ioux[v * M3 + 2 * M + e] + biouh[2 * M + e];
        float c  = sigf(i0) * tanhf(i2);
        g_cleaf[i] = c;
        g_hleaf[i] = sigf(i1) * tanhf(c);
    }
    gsync();

    // ------- Phase 2: pend counts + hfW table + scan part A ---------------
    for (int i = gid; i < TOT; i += gs) {
        int loc = i & (NNODE - 1);
        if (loc && __ldcg(&g_nchild[i]) > 0) {
            int tree = i >> 16;
            const int* parp = tree ? r_par : l_par;
            atomicAdd(&g_pend[(tree << 16) + __ldg(parp + loc)], 1);
        }
    }
    {
        const int VG = VOCAB / VNB;   // 125
        for (int g = blockIdx.x; g < VG; g += gridDim.x) {
            #pragma unroll
            for (int n = 0; n < VNB; n++)
                s_f[n * M + t] = g_hleaf[(g * VNB + n) * M + t];
            __syncthreads();
            float bf[VNB];
            #pragma unroll
            for (int n = 0; n < VNB; n++) bf[n] = bfh_t;
            #pragma unroll 1
            for (int k = 0; k < M; k += 4) {
                #pragma unroll
                for (int kk = 0; kk < 4; kk++) {
                    float w = Wfh[(k + kk) * M + t];
                    #pragma unroll
                    for (int n = 0; n < VNB; n++)
                        bf[n] += s_f[n * M + k + kk] * w;
                }
            }
            #pragma unroll
            for (int n = 0; n < VNB; n++)
                g_hfw[(g * VNB + n) * M + t] = bf[n];
            __syncthreads();
        }
    }
    {
        // per-block partial sum of nchild over its chunk
        const int chunk = (TOT + G - 1) / G;
        const int lo = blockIdx.x * chunk;
        const int hi = min(TOT, lo + chunk);
        int local = 0;
        for (int i = lo + t; i < hi; i += 256) local += __ldcg(&g_nchild[i]);
        s_red[t] = local;
        __syncthreads();
        for (int s = 128; s > 0; s >>= 1) {
            if (t < s) s_red[t] += s_red[t + s];
            __syncthreads();
        }
        if (t == 0) g_bsum[blockIdx.x] = s_red[0];
    }
    gsync();

    // ------- Phase 3: serial scan of block sums (tiny) --------------------
    if (blockIdx.x == 0 && t == 0) {
        int run = 0;
        for (int b = 0; b < G; b++) {
            int s = __ldcg(&g_bsum[b]);
            g_bsum[b] = run;
            run += s;
        }
    }
    gsync();

    // ------- Phase 4a: within-chunk exclusive scan (smem staged) ----------
    {
        const int chunk = (TOT + G - 1) / G;
        const int lo = blockIdx.x * chunk;
        const int hi = min(TOT, lo + chunk);
        int* s_i = reinterpret_cast<int*>(s_f);    // 4096 ints >= chunk
        for (int i = lo + t; i < hi; i += 256) s_i[i - lo] = __ldcg(&g_nchild[i]);
        __syncthreads();
        if (t == 0) {
            int run = __ldcg(&g_bsum[blockIdx.x]);
            for (int i = 0; i < hi - lo; i++) { int c = s_i[i]; s_i[i] = run; run += c; }
        }
        __syncthreads();
        for (int i = lo + t; i < hi; i += 256) {
            g_cstart[i] = s_i[i - lo];
            g_ccur[i]   = s_i[i - lo];
        }
    }
    gsync();

    // ------- Phase 4b: CSR fill + round-0 classify ------------------------
    for (int i = gid; i < TOT; i += gs) {
        int tree = i >> 16, loc = i & (NNODE - 1);
        if (loc) {
            const int* parp = tree ? r_par : l_par;
            const int* tokp = tree ? r_tok : l_tok;
            int pg = (tree << 16) + __ldg(parp + loc);
            int slot = atomicAdd(&g_ccur[pg], 1);
            int isleaf = (__ldcg(&g_nchild[i]) == 0);
            g_child[slot] = isleaf ? (int)(0x80000000u | (unsigned)tokp[loc]) : i;
        }
        if (__ldcg(&g_nchild[i]) > 0 && __ldcg(&g_pend[i]) == 0)
            g_order[atomicAdd(&g_alloc, 1)] = i;
    }
    gsync();   // snapshots g_alloc -> g_re (round 0 boundary)

    // ------- Phase 5: round loop with intra-round wave splitting ----------
    {
        int rs = 0;
        int re = __ldcg(&g_re);
        while (rs < re) {
            int cnt = re - rs;
            // (a) exactly-full NT=16 waves: zero imbalance, max weight reuse
            const int fullN = (cnt / (16 * G)) * (16 * G);
            if (fullN > 0) {
                do_round<16>(rs, fullN, l_tok, l_par, r_tok, r_par, Wiouh, Wfh,
                             bio0, bio1, bio2, bfh_t, s_f, s_fc,
                             s_node, s_tok, s_parg, s_ptok, s_cs, s_ce);
                rs  += fullN;
                cnt -= fullN;
            }
            // (b) remainder (< 16*G nodes): one wave, cost-model NT pick
            if (cnt > 0) {
                long best = 0x7fffffffffffL; int bestNT = 16;
                #pragma unroll
                for (int ntI = 0; ntI < 5; ntI++) {
                    const int NTc = (ntI == 0) ? 16 : (ntI == 1) ? 8 : (ntI == 2) ? 4
                                  : (ntI == 3) ? 2 : 1;
                    int grp = (cnt + NTc - 1) / NTc;
                    int bat = (grp + G - 1) / G;
                    int gw  = grp < G ? grp : G;
                    int wc  = NTc * 455;
                    if (gw * 10 > wc) wc = gw * 10;
                    if (wc < 250) wc = 250;
                    long c = (long)bat * wc;
                    if (c < best) { best = c; bestNT = NTc; }
                }
                if (bestNT == 16)
                    do_round<16>(rs, cnt, l_tok, l_par, r_tok, r_par, Wiouh, Wfh,
                                 bio0, bio1, bio2, bfh_t, s_f, s_fc,
                                 s_node, s_tok, s_parg, s_ptok, s_cs, s_ce);
                else if (bestNT == 8)
                    do_round<8>(rs, cnt, l_tok, l_par, r_tok, r_par, Wiouh, Wfh,
                                bio0, bio1, bio2, bfh_t, s_f, s_fc,
                                s_node, s_tok, s_parg, s_ptok, s_cs, s_ce);
                else if (bestNT == 4)
                    do_round<4>(rs, cnt, l_tok, l_par, r_tok, r_par, Wiouh, Wfh,
                                bio0, bio1, bio2, bfh_t, s_f, s_fc,
                                s_node, s_tok, s_parg, s_ptok, s_cs, s_ce);
                else if (bestNT == 2)
                    do_round<2>(rs, cnt, l_tok, l_par, r_tok, r_par, Wiouh, Wfh,
                                bio0, bio1, bio2, bfh_t, s_f, s_fc,
                                s_node, s_tok, s_parg, s_ptok, s_cs, s_ce);
                else
                    do_round<1>(rs, cnt, l_tok, l_par, r_tok, r_par, Wiouh, Wfh,
                                bio0, bio1, bio2, bfh_t, s_f, s_fc,
                                s_node, s_tok, s_parg, s_ptok, s_cs, s_ce);
            }
            gsync();                      // drains stores + snapshots next re
            rs = re;
            re = __ldcg(&g_re);
        }
    }

    // ------- Phase 6: similarity head (block 0) ----------------------------
    if (blockIdx.x == 0) {
        float cl = __ldcg(&g_croot[t]);
        float cr = __ldcg(&g_croot[M + t]);
        s_f[t]     = cl * cr;
        s_f[M + t] = fabsf(cl - cr);
        __syncthreads();
        float acc = bh[t];
        for (int k = 0; k < 2 * M; k++) acc += s_f[k] * Wh[k * M + t];
        float hid = sigf(acc);
        s_f[2 * M + t] = hid * Wp[2 * t];
        s_f[3 * M + t] = hid * Wp[2 * t + 1];
        __syncthreads();
        if (t == 0) {
            float l0 = bp[0], l1 = bp[1];
            for (int k = 0; k < M; k++) { l0 += s_f[2 * M + k]; l1 += s_f[3 * M + k]; }
            float mx = fmaxf(l0, l1);
            float e0 = expf(l0 - mx), e1 = expf(l1 - mx);
            float inv = 1.0f / (e0 + e1);
            out[0] = e0 * inv;
            out[1] = e1 * inv;
        }
    }
}

extern "C" void kernel_launch(void* const* d_in, const int* in_sizes, int n_in,
                              void* d_out, int out_size)
{
    (void)in_sizes; (void)n_in; (void)out_size;
    int dev = 0;
    cudaGetDevice(&dev);
    int nsm = 0;
    cudaDeviceGetAttribute(&nsm, cudaDevAttrMultiProcessorCount, dev);
    if (nsm <= 0) nsm = 148;

    treelstm_kernel<<<2 * nsm, 256>>>(
        (const int*)d_in[0], (const int*)d_in[1],
        (const int*)d_in[2], (const int*)d_in[3],
        (const float*)d_in[4],
        (const float*)d_in[5], (const float*)d_in[6],
        (const float*)d_in[7], (const float*)d_in[8],
        (const float*)d_in[9], (const float*)d_in[10],
        (const float*)d_in[11], (const float*)d_in[12],
        (const float*)d_in[13], (const float*)d_in[14],
        (const float*)d_in[15], (const float*)d_in[16],
        (float*)d_out);
}

// round 16
// speedup vs baseline: 1.2631x; 1.0964x over previous
#include <cuda_runtime.h>
#include <math.h>

// SimilarityTreeLSTM on GB300: persistent kernel, height-frontier rounds.
//
// R16 = R15 (CSR gather, wave splitting) + register-level pre-leaf fold:
//  * hwl[v] = h_leaf[v] @ Wiouh vocab table (3MB, L2-hot). During the CSR
//    gather, leaf children fold into the iou accumulators a0..a2 IN
//    REGISTERS (no accumulator array -- fixes R9/R10's DRAM failure mode).
//  * round 0 == nodes whose children are ALL leaves (pushed sets require an
//    internal child) -> h_sum==0 -> Wiouh matvec skipped (196K of 262K MACs)
//    for ~half the internal nodes. Rounds >=1 algebraically unchanged.

#define NNODE 65536
#define TOT   (2 * NNODE)
#define M     256
#define M3    (3 * M)
#define VOCAB 1000
#define VNB   8

// ---------------- device scratch (static: no allocations allowed) ----------
__device__ float g_h[TOT * M];           // internal node h (written once)
__device__ float g_fc[TOT * M];          // internal node f*c (written once)
__device__ float g_ioux[VOCAB * M3];     // vocab proj: emb@Wioux + bioux
__device__ float g_fxp[VOCAB * M];       // vocab proj: emb@Wfx + bfx
__device__ float g_hleaf[VOCAB * M];     // leaf h by token
__device__ float g_cleaf[VOCAB * M];     // leaf c by token
__device__ float g_hfw[VOCAB * M];       // h_leaf @ Wfh + bfh
__device__ float g_hwl[VOCAB * M3];      // h_leaf @ Wiouh
__device__ int   g_nchild[TOT];
__device__ int   g_pend[TOT];            // remaining internal children
__device__ int   g_cstart[TOT];          // CSR segment start
__device__ int   g_ccur[TOT];            // CSR fill cursor
__device__ int   g_child[TOT];           // CSR entries (<0: leaf, low bits=token)
__device__ int   g_bsum[1024];           // per-block partial sums for scan
__device__ int   g_order[TOT];           // append-only ready list
__device__ int   g_alloc;                // next free slot in g_order
__device__ int   g_re;                   // round-end snapshot (set in barrier)
__device__ float g_croot[2 * M];
__device__ unsigned g_barcnt;
__device__ unsigned g_sense;

__device__ __forceinline__ float sigf(float x) {
    return 1.0f / (1.0f + expf(-x));
}

// Sense-reversal grid barrier; last arriver snapshots g_alloc into g_re.
__device__ __forceinline__ void gsync() {
    __syncthreads();
    if (threadIdx.x == 0) {
        __threadfence();
        unsigned target = *((volatile unsigned*)&g_sense) + 1u;
        unsigned a = atomicAdd(&g_barcnt, 1u);
        if (a == gridDim.x - 1u) {
            g_barcnt = 0u;
            g_re = *((volatile int*)&g_alloc);
            __threadfence();
            atomicExch(&g_sense, target);
        } else {
            while (*((volatile unsigned*)&g_sense) != target) { __nanosleep(64); }
        }
        __threadfence();
    }
    __syncthreads();
}

// Process one batch of nn nodes; caller pre-filled s_node[t] (clamped) for t<NT.
// MATVEC=false: round-0 nodes (all children are leaves) -> no Wiouh matvec.
template <int NT, bool MATVEC>
__device__ void do_group(int nn,
                         const int* __restrict__ l_tok, const int* __restrict__ l_par,
                         const int* __restrict__ r_tok, const int* __restrict__ r_par,
                         const float* __restrict__ Wiouh, const float* __restrict__ Wfh,
                         float bio0, float bio1, float bio2, float bfh_t,
                         float* s_f, float* s_fc,
                         int* s_node, int* s_tok, int* s_parg, int* s_ptok,
                         int* s_cs, int* s_ce)
{
    const int t = threadIdx.x;

    if (t < NT) {
        int node = s_node[t];
        int tree = node >> 16, loc = node & (NNODE - 1);
        const int* tokp = tree ? r_tok : l_tok;
        const int* parp = tree ? r_par : l_par;
        int pl = parp[loc];
        s_tok[t]  = tokp[loc];
        s_parg[t] = (tree << 16) + pl;
        s_ptok[t] = tokp[pl];
        s_cs[t]   = __ldcg(&g_cstart[node]);
        s_ce[t]   = s_cs[t] + __ldcg(&g_nchild[node]);
    }
    __syncthreads();

    // gather: leaf children fold fcs (hfw) AND iou (hwl) in registers;
    // internal children (MATVEC rounds only) accumulate h/fc sums.
    float a0[NT], a1[NT], a2[NT];
    #pragma unroll
    for (int n = 0; n < NT; n++) {
        int tk = s_tok[n];
        float t0 = g_ioux[tk * M3 + t]         + bio0;
        float t1 = g_ioux[tk * M3 + M + t]     + bio1;
        float t2 = g_ioux[tk * M3 + 2 * M + t] + bio2;
        float hs = 0.f, fcs = 0.f;
        const float fxv = g_fxp[tk * M + t];
        const int ce = s_ce[n];
        for (int j = s_cs[n]; j < ce; j++) {
            int e = __ldg(&g_child[j]);
            if (e < 0) {
                int v = e & 0xFFFF;
                fcs += sigf(g_hfw[v * M + t] + fxv) * g_cleaf[v * M + t];
                t0  += g_hwl[v * M3 + t];
                t1  += g_hwl[v * M3 + M + t];
                t2  += g_hwl[v * M3 + 2 * M + t];
            } else if (MATVEC) {
                hs  += __ldcg(&g_h[(long)e * M + t]);
                fcs += __ldcg(&g_fc[(long)e * M + t]);
            }
        }
        if (MATVEC) s_f[n * M + t] = hs;
        s_fc[n * M + t] = fcs;
        a0[n] = t0; a1[n] = t1; a2[n] = t2;
    }
    __syncthreads();

    if (MATVEC) {
        // ---- Wiouh matvec: explicit two-phase weight double-buffer ----
        float wa0[4], wa1[4], wa2[4], wb0[4], wb1[4], wb2[4];
        #pragma unroll
        for (int kk = 0; kk < 4; kk++) {
            wa0[kk] = Wiouh[kk * M3 + t];
            wa1[kk] = Wiouh[kk * M3 + M + t];
            wa2[kk] = Wiouh[kk * M3 + 2 * M + t];
        }
        #pragma unroll 1
        for (int k = 0; k < M; k += 8) {
            #pragma unroll
            for (int kk = 0; kk < 4; kk++) {
                wb0[kk] = Wiouh[(k + 4 + kk) * M3 + t];
                wb1[kk] = Wiouh[(k + 4 + kk) * M3 + M + t];
                wb2[kk] = Wiouh[(k + 4 + kk) * M3 + 2 * M + t];
            }
            #pragma unroll
            for (int n = 0; n < NT; n++) {
                const float4 h4 = *reinterpret_cast<const float4*>(s_f + n * M + k);
                a0[n] += h4.x * wa0[0]; a1[n] += h4.x * wa1[0]; a2[n] += h4.x * wa2[0];
                a0[n] += h4.y * wa0[1]; a1[n] += h4.y * wa1[1]; a2[n] += h4.y * wa2[1];
                a0[n] += h4.z * wa0[2]; a1[n] += h4.z * wa1[2]; a2[n] += h4.z * wa2[2];
                a0[n] += h4.w * wa0[3]; a1[n] += h4.w * wa1[3]; a2[n] += h4.w * wa2[3];
            }
            if (k + 8 < M) {
                #pragma unroll
                for (int kk = 0; kk < 4; kk++) {
                    wa0[kk] = Wiouh[(k + 8 + kk) * M3 + t];
                    wa1[kk] = Wiouh[(k + 8 + kk) * M3 + M + t];
                    wa2[kk] = Wiouh[(k + 8 + kk) * M3 + 2 * M + t];
                }
            }
            #pragma unroll
            for (int n = 0; n < NT; n++) {
                const float4 h4 = *reinterpret_cast<const float4*>(s_f + n * M + k + 4);
                a0[n] += h4.x * wb0[0]; a1[n] += h4.x * wb1[0]; a2[n] += h4.x * wb2[0];
                a0[n] += h4.y * wb0[1]; a1[n] += h4.y * wb1[1]; a2[n] += h4.y * wb2[1];
                a0[n] += h4.z * wb0[2]; a1[n] += h4.z * wb1[2]; a2[n] += h4.z * wb2[2];
                a0[n] += h4.w * wb0[3]; a1[n] += h4.w * wb1[3]; a2[n] += h4.w * wb2[3];
            }
        }
    }

    float cv[NT], hv[NT];
    #pragma unroll
    for (int n = 0; n < NT; n++) {
        float fc = s_fc[n * M + t];
        float ig = sigf(a0[n]);
        float og = sigf(a1[n]);
        float ug = tanhf(a2[n]);
        cv[n] = ig * ug + fc;
        hv[n] = og * tanhf(cv[n]);
    }
    __syncthreads();                 // s_f reuse boundary
    #pragma unroll
    for (int n = 0; n < NT; n++) s_f[n * M + t] = hv[n];
    __syncthreads();

    float b[NT];
    #pragma unroll
    for (int n = 0; n < NT; n++)
        b[n] = bfh_t + g_fxp[s_ptok[n] * M + t];

    // ---- Wfh matvec: explicit two-phase weight double-buffer ----
    {
        float wa[4], wb[4];
        #pragma unroll
        for (int kk = 0; kk < 4; kk++)
            wa[kk] = Wfh[kk * M + t];
        #pragma unroll 1
        for (int k = 0; k < M; k += 8) {
            #pragma unroll
            for (int kk = 0; kk < 4; kk++)
                wb[kk] = Wfh[(k + 4 + kk) * M + t];
            #pragma unroll
            for (int n = 0; n < NT; n++) {
                const float4 h4 = *reinterpret_cast<const float4*>(s_f + n * M + k);
                b[n] += h4.x * wa[0] + h4.y * wa[1] + h4.z * wa[2] + h4.w * wa[3];
            }
            if (k + 8 < M) {
                #pragma unroll
                for (int kk = 0; kk < 4; kk++)
                    wa[kk] = Wfh[(k + 8 + kk) * M + t];
            }
            #pragma unroll
            for (int n = 0; n < NT; n++) {
                const float4 h4 = *reinterpret_cast<const float4*>(s_f + n * M + k + 4);
                b[n] += h4.x * wb[0] + h4.y * wb[1] + h4.z * wb[2] + h4.w * wb[3];
            }
        }
    }

    // plain stores (no atomics): each internal node writes its own rows
    #pragma unroll
    for (int n = 0; n < NT; n++) {
        if (n < nn) {
            int node = s_node[n];
            if (node & (NNODE - 1)) {        // not a root
                float f = sigf(b[n]);
                g_h[(long)node * M + t]  = hv[n];
                g_fc[(long)node * M + t] = f * cv[n];
            } else {
                g_croot[(node >> 16) * M + t] = cv[n];
            }
        }
    }
    __syncthreads();
    // last-finishing child pushes parent (consumed only after next gsync,
    // whose fences make both the data stores and this push visible)
    if (t < nn) {
        int node = s_node[t];
        if (node & (NNODE - 1)) {
            int pg = s_parg[t];
            if (atomicSub(&g_pend[pg], 1) == 1) {
                int pos = atomicAdd(&g_alloc, 1);
                g_order[pos] = pg;
            }
        }
    }
    __syncthreads();
}

// Round mode: process [rs, rs+cnt) of g_order, NT nodes per group.
template <int NT, bool MATVEC>
__device__ void do_round(int rs, int cnt,
                         const int* __restrict__ l_tok, const int* __restrict__ l_par,
                         const int* __restrict__ r_tok, const int* __restrict__ r_par,
                         const float* __restrict__ Wiouh, const float* __restrict__ Wfh,
                         float bio0, float bio1, float bio2, float bfh_t,
                         float* s_f, float* s_fc,
                         int* s_node, int* s_tok, int* s_parg, int* s_ptok,
                         int* s_cs, int* s_ce)
{
    const int t = threadIdx.x;
    const int ngrp = (cnt + NT - 1) / NT;
    for (int g = blockIdx.x; g < ngrp; g += gridDim.x) {
        const int base = rs + g * NT;
        const int nn   = min(NT, cnt - g * NT);
        if (t < NT)
            s_node[t] = __ldcg(&g_order[base + ((t < nn) ? t : 0)]);
        do_group<NT, MATVEC>(nn, l_tok, l_par, r_tok, r_par, Wiouh, Wfh,
                             bio0, bio1, bio2, bfh_t, s_f, s_fc,
                             s_node, s_tok, s_parg, s_ptok, s_cs, s_ce);
    }
}

// Remainder wave: cost-model NT pick over {16,8,4,2,1}.
template <bool MATVEC>
__device__ __forceinline__ void do_rem(int rs, int cnt, int G, int fmaw,
    const int* l_tok, const int* l_par, const int* r_tok, const int* r_par,
    const float* Wiouh, const float* Wfh,
    float bio0, float bio1, float bio2, float bfh_t,
    float* s_f, float* s_fc,
    int* s_node, int* s_tok, int* s_parg, int* s_ptok, int* s_cs, int* s_ce)
{
    long best = 0x7fffffffffffL; int bestNT = 16;
    #pragma unroll
    for (int ntI = 0; ntI < 5; ntI++) {
        const int NTc = (ntI == 0) ? 16 : (ntI == 1) ? 8 : (ntI == 2) ? 4
                      : (ntI == 3) ? 2 : 1;
        int grp = (cnt + NTc - 1) / NTc;
        int bat = (grp + G - 1) / G;
        int gw  = grp < G ? grp : G;
        int wc  = NTc * fmaw;
        if (gw * 10 > wc) wc = gw * 10;
        if (wc < 250) wc = 250;
        long c = (long)bat * wc;
        if (c < best) { best = c; bestNT = NTc; }
    }
    if (bestNT == 16)
        do_round<16, MATVEC>(rs, cnt, l_tok, l_par, r_tok, r_par, Wiouh, Wfh,
                             bio0, bio1, bio2, bfh_t, s_f, s_fc,
                             s_node, s_tok, s_parg, s_ptok, s_cs, s_ce);
    else if (bestNT == 8)
        do_round<8, MATVEC>(rs, cnt, l_tok, l_par, r_tok, r_par, Wiouh, Wfh,
                            bio0, bio1, bio2, bfh_t, s_f, s_fc,
                            s_node, s_tok, s_parg, s_ptok, s_cs, s_ce);
    else if (bestNT == 4)
        do_round<4, MATVEC>(rs, cnt, l_tok, l_par, r_tok, r_par, Wiouh, Wfh,
                            bio0, bio1, bio2, bfh_t, s_f, s_fc,
                            s_node, s_tok, s_parg, s_ptok, s_cs, s_ce);
    else if (bestNT == 2)
        do_round<2, MATVEC>(rs, cnt, l_tok, l_par, r_tok, r_par, Wiouh, Wfh,
                            bio0, bio1, bio2, bfh_t, s_f, s_fc,
                            s_node, s_tok, s_parg, s_ptok, s_cs, s_ce);
    else
        do_round<1, MATVEC>(rs, cnt, l_tok, l_par, r_tok, r_par, Wiouh, Wfh,
                            bio0, bio1, bio2, bfh_t, s_f, s_fc,
                            s_node, s_tok, s_parg, s_ptok, s_cs, s_ce);
}

extern "C" __global__ void __launch_bounds__(256, 2)
treelstm_kernel(const int* __restrict__ l_tok, const int* __restrict__ l_par,
                const int* __restrict__ r_tok, const int* __restrict__ r_par,
                const float* __restrict__ emb,
                const float* __restrict__ Wioux, const float* __restrict__ bioux,
                const float* __restrict__ Wiouh, const float* __restrict__ biouh,
                const float* __restrict__ Wfx,   const float* __restrict__ bfx,
                const float* __restrict__ Wfh,   const float* __restrict__ bfh,
                const float* __restrict__ Wh,    const float* __restrict__ bh,
                const float* __restrict__ Wp,    const float* __restrict__ bp,
                float* __restrict__ out)
{
    __shared__ __align__(16) float s_f[16 * M];    // 16 KB
    __shared__ __align__(16) float s_fc[16 * M];   // 16 KB
    __shared__ int s_node[16], s_tok[16], s_parg[16], s_ptok[16];
    __shared__ int s_cs[16], s_ce[16];
    __shared__ int s_red[256];

    const int t   = threadIdx.x;
    const int gid = blockIdx.x * blockDim.x + threadIdx.x;
    const int gs  = gridDim.x * blockDim.x;
    const int G   = gridDim.x;

    // ------- Phase 0: init + vocab projections ----------------------------
    {
        for (int i = gid; i < TOT; i += gs) { g_nchild[i] = 0; g_pend[i] = 0; }
        if (gid == 0) g_alloc = 0;

        const int VG = VOCAB / VNB;   // 125
        for (int g = blockIdx.x; g < VG; g += gridDim.x) {
            #pragma unroll
            for (int n = 0; n < VNB; n++)
                s_f[n * M + t] = emb[(g * VNB + n) * M + t];
            __syncthreads();
            float a0[VNB], a1[VNB], a2[VNB], af[VNB];
            #pragma unroll
            for (int n = 0; n < VNB; n++) {
                a0[n] = bioux[t]; a1[n] = bioux[M + t];
                a2[n] = bioux[2 * M + t]; af[n] = bfx[t];
            }
            #pragma unroll 1
            for (int k = 0; k < M; k += 4) {
                #pragma unroll
                for (int kk = 0; kk < 4; kk++) {
                    float w0 = Wioux[(k + kk) * M3 + t];
                    float w1 = Wioux[(k + kk) * M3 + M + t];
                    float w2 = Wioux[(k + kk) * M3 + 2 * M + t];
                    float wf = Wfx[(k + kk) * M + t];
                    #pragma unroll
                    for (int n = 0; n < VNB; n++) {
                        float xv = s_f[n * M + k + kk];
                        a0[n] += xv * w0; a1[n] += xv * w1;
                        a2[n] += xv * w2; af[n] += xv * wf;
                    }
                }
            }
            #pragma unroll
            for (int n = 0; n < VNB; n++) {
                int v = g * VNB + n;
                g_ioux[v * M3 + t]         = a0[n];
                g_ioux[v * M3 + M + t]     = a1[n];
                g_ioux[v * M3 + 2 * M + t] = a2[n];
                g_fxp[v * M + t]           = af[n];
            }
            __syncthreads();
        }
    }
    gsync();

    // loop-invariant biases
    const float bio0 = biouh[t], bio1 = biouh[M + t], bio2 = biouh[2 * M + t];
    const float bfh_t = bfh[t];

    // ------- Phase 1: child counts + leaf h/c tables ----------------------
    for (int i = gid; i < TOT; i += gs) {
        int tree = i >> 16, loc = i & (NNODE - 1);
        if (loc) {
            const int* parp = tree ? r_par : l_par;
            atomicAdd(&g_nchild[(tree << 16) + __ldg(parp + loc)], 1);
        }
    }
    for (int i = gid; i < VOCAB * M; i += gs) {
        int v = i / M, e = i % M;
        float i0 = g_ioux[v * M3 + e]         + biouh[e];
        float i1 = g_ioux[v * M3 + M + e]     + biouh[M + e];
        float i2 = g_ioux[v * M3 + 2 * M + e] + biouh[2 * M + e];
        float c  = sigf(i0) * tanhf(i2);
        g_cleaf[i] = c;
        g_hleaf[i] = sigf(i1) * tanhf(c);
    }
    gsync();

    // ------- Phase 2: pend counts + hwl/hfw tables + scan part A ----------
    for (int i = gid; i < TOT; i += gs) {
        int loc = i & (NNODE - 1);
        if (loc && __ldcg(&g_nchild[i]) > 0) {
            int tree = i >> 16;
            const int* parp = tree ? r_par : l_par;
            atomicAdd(&g_pend[(tree << 16) + __ldg(parp + loc)], 1);
        }
    }
    {
        // hwl = h_leaf @ Wiouh ; hfw = h_leaf @ Wfh + bfh
        const int VG = VOCAB / VNB;   // 125
        for (int g = blockIdx.x; g < VG; g += gridDim.x) {
            #pragma unroll
            for (int n = 0; n < VNB; n++)
                s_f[n * M + t] = g_hleaf[(g * VNB + n) * M + t];
            __syncthreads();
            float a0[VNB], a1[VNB], a2[VNB], bf[VNB];
            #pragma unroll
            for (int n = 0; n < VNB; n++) {
                a0[n] = 0.f; a1[n] = 0.f; a2[n] = 0.f; bf[n] = bfh_t;
            }
            #pragma unroll 1
            for (int k = 0; k < M; k += 4) {
                #pragma unroll
                for (int kk = 0; kk < 4; kk++) {
                    float w0 = Wiouh[(k + kk) * M3 + t];
                    float w1 = Wiouh[(k + kk) * M3 + M + t];
                    float w2 = Wiouh[(k + kk) * M3 + 2 * M + t];
                    float wf = Wfh[(k + kk) * M + t];
                    #pragma unroll
                    for (int n = 0; n < VNB; n++) {
                        float xv = s_f[n * M + k + kk];
                        a0[n] += xv * w0; a1[n] += xv * w1;
                        a2[n] += xv * w2; bf[n] += xv * wf;
                    }
                }
            }
            #pragma unroll
            for (int n = 0; n < VNB; n++) {
                int v = g * VNB + n;
                g_hwl[v * M3 + t]         = a0[n];
                g_hwl[v * M3 + M + t]     = a1[n];
                g_hwl[v * M3 + 2 * M + t] = a2[n];
                g_hfw[v * M + t]          = bf[n];
            }
            __syncthreads();
        }
    }
    {
        // per-block partial sum of nchild over its chunk
        const int chunk = (TOT + G - 1) / G;
        const int lo = blockIdx.x * chunk;
        const int hi = min(TOT, lo + chunk);
        int local = 0;
        for (int i = lo + t; i < hi; i += 256) local += __ldcg(&g_nchild[i]);
        s_red[t] = local;
        __syncthreads();
        for (int s = 128; s > 0; s >>= 1) {
            if (t < s) s_red[t] += s_red[t + s];
            __syncthreads();
        }
        if (t == 0) g_bsum[blockIdx.x] = s_red[0];
    }
    gsync();

    // ------- Phase 3: serial scan of block sums (tiny) --------------------
    if (blockIdx.x == 0 && t == 0) {
        int run = 0;
        for (int b = 0; b < G; b++) {
            int s = __ldcg(&g_bsum[b]);
            g_bsum[b] = run;
            run += s;
        }
    }
    gsync();

    // ------- Phase 4a: within-chunk exclusive scan (smem staged) ----------
    {
        const int chunk = (TOT + G - 1) / G;
        const int lo = blockIdx.x * chunk;
        const int hi = min(TOT, lo + chunk);
        int* s_i = reinterpret_cast<int*>(s_f);    // 4096 ints >= chunk
        for (int i = lo + t; i < hi; i += 256) s_i[i - lo] = __ldcg(&g_nchild[i]);
        __syncthreads();
        if (t == 0) {
            int run = __ldcg(&g_bsum[blockIdx.x]);
            for (int i = 0; i < hi - lo; i++) { int c = s_i[i]; s_i[i] = run; run += c; }
        }
        __syncthreads();
        for (int i = lo + t; i < hi; i += 256) {
            g_cstart[i] = s_i[i - lo];
            g_ccur[i]   = s_i[i - lo];
        }
    }
    gsync();

    // ------- Phase 4b: CSR fill + round-0 classify ------------------------
    for (int i = gid; i < TOT; i += gs) {
        int tree = i >> 16, loc = i & (NNODE - 1);
        if (loc) {
            const int* parp = tree ? r_par : l_par;
            const int* tokp = tree ? r_tok : l_tok;
            int pg = (tree << 16) + __ldg(parp + loc);
            int slot = atomicAdd(&g_ccur[pg], 1);
            int isleaf = (__ldcg(&g_nchild[i]) == 0);
            g_child[slot] = isleaf ? (int)(0x80000000u | (unsigned)tokp[loc]) : i;
        }
        if (__ldcg(&g_nchild[i]) > 0 && __ldcg(&g_pend[i]) == 0)
            g_order[atomicAdd(&g_alloc, 1)] = i;
    }
    gsync();   // snapshots g_alloc -> g_re (round 0 boundary)

    // ------- Phase 5: round loop (round 0 = lite, no Wiouh matvec) --------
    {
        int rs = 0;
        int re = __ldcg(&g_re);
        bool lite = true;
        while (rs < re) {
            int cnt = re - rs;
            const int fullN = (cnt / (16 * G)) * (16 * G);
            if (lite) {
                if (fullN > 0) {
                    do_round<16, false>(rs, fullN, l_tok, l_par, r_tok, r_par,
                                        Wiouh, Wfh, bio0, bio1, bio2, bfh_t,
                                        s_f, s_fc, s_node, s_tok, s_parg, s_ptok,
                                        s_cs, s_ce);
                    rs += fullN; cnt -= fullN;
                }
                if (cnt > 0)
                    do_rem<false>(rs, cnt, G, 150, l_tok, l_par, r_tok, r_par,
                                  Wiouh, Wfh, bio0, bio1, bio2, bfh_t,
                                  s_f, s_fc, s_node, s_tok, s_parg, s_ptok,
                                  s_cs, s_ce);
            } else {
                if (fullN > 0) {
                    do_round<16, true>(rs, fullN, l_tok, l_par, r_tok, r_par,
                                       Wiouh, Wfh, bio0, bio1, bio2, bfh_t,
                                       s_f, s_fc, s_node, s_tok, s_parg, s_ptok,
                                       s_cs, s_ce);
                    rs += fullN; cnt -= fullN;
                }
                if (cnt > 0)
                    do_rem<true>(rs, cnt, G, 455, l_tok, l_par, r_tok, r_par,
                                 Wiouh, Wfh, bio0, bio1, bio2, bfh_t,
                                 s_f, s_fc, s_node, s_tok, s_parg, s_ptok,
                                 s_cs, s_ce);
            }
            gsync();                      // drains stores + snapshots next re
            rs = re;
            re = __ldcg(&g_re);
            lite = false;
        }
    }

    // ------- Phase 6: similarity head (block 0) ----------------------------
    if (blockIdx.x == 0) {
        float cl = __ldcg(&g_croot[t]);
        float cr = __ldcg(&g_croot[M + t]);
        s_f[t]     = cl * cr;
        s_f[M + t] = fabsf(cl - cr);
        __syncthreads();
        float acc = bh[t];
        for (int k = 0; k < 2 * M; k++) acc += s_f[k] * Wh[k * M + t];
        float hid = sigf(acc);
        s_f[2 * M + t] = hid * Wp[2 * t];
        s_f[3 * M + t] = hid * Wp[2 * t + 1];
        __syncthreads();
        if (t == 0) {
            float l0 = bp[0], l1 = bp[1];
            for (int k = 0; k < M; k++) { l0 += s_f[2 * M + k]; l1 += s_f[3 * M + k]; }
            float mx = fmaxf(l0, l1);
            float e0 = expf(l0 - mx), e1 = expf(l1 - mx);
            float inv = 1.0f / (e0 + e1);
            out[0] = e0 * inv;
            out[1] = e1 * inv;
        }
    }
}

extern "C" void kernel_launch(void* const* d_in, const int* in_sizes, int n_in,
                              void* d_out, int out_size)
{
    (void)in_sizes; (void)n_in; (void)out_size;
    int dev = 0;
    cudaGetDevice(&dev);
    int nsm = 0;
    cudaDeviceGetAttribute(&nsm, cudaDevAttrMultiProcessorCount, dev);
    if (nsm <= 0) nsm = 148;

    treelstm_kernel<<<2 * nsm, 256>>>(
        (const int*)d_in[0], (const int*)d_in[1],
        (const int*)d_in[2], (const int*)d_in[3],
        (const float*)d_in[4],
        (const float*)d_in[5], (const float*)d_in[6],
        (const float*)d_in[7], (const float*)d_in[8],
        (const float*)d_in[9], (const float*)d_in[10],
        (const float*)d_in[11], (const float*)d_in[12],
        (const float*)d_in[13], (const float*)d_in[14],
        (const float*)d_in[15], (const float*)d_in[16],
        (float*)d_out);
}